// round 1
// baseline (speedup 1.0000x reference)
#include <cuda_runtime.h>

// Problem constants (fixed by setup_inputs: img [1,1,544,960], T=8, R=4)
#define H  544
#define W  960
#define T  8
#define R  4
#define HB (H/T)                  // 68
#define WB (W/T)                  // 120
#define NC ((2*R+1)*(2*R+1))      // 81 candidates
#define WIN (T + 2*R)             // 16

// ---------------- scratch (device globals; no cudaMalloc allowed) ----------
__device__ float         g_cur_blur[H*W];
__device__ unsigned char g_cur_q[H*W];
__device__ unsigned char g_prev_q[H*W];
__device__ char2         g_vec[HB*WB];     // (vy, vx) = (-dy, -dx), ints in [-4,4]
__device__ int           g_spiral[NC];     // spiral rank per candidate (1..81)

// ---------------- spiral tie-break LUT -------------------------------------
__global__ void spiral_init_kernel() {
    if (threadIdx.x == 0 && blockIdx.x == 0) {
        int n = 0;
        for (int dy = 0; dy <= R; dy++) {
            for (int dir = 0; dir < 4; dir++) {
                int limit = (dir == 0 && dy == 0) ? 1 : dy;
                for (int dx = -dy; dx < limit; dx++) {
                    int wx, wy;
                    if (dir == 0)      { wx = R + dx; wy = R + dy; }
                    else if (dir == 1) { wx = R + dy; wy = R - dx; }
                    else if (dir == 2) { wx = R - dx; wy = R - dy; }
                    else               { wx = R - dy; wy = R + dx; }
                    n++;
                    g_spiral[wy * (2*R+1) + wx] = n;
                }
            }
        }
    }
}

// ---------------- binomial blur + uint8 quantization -----------------------
__device__ __forceinline__ float blur_at(const float* __restrict__ img, int y, int x) {
    int yu = max(y - 1, 0);
    int yd = min(y + 1, H - 1);
    float v[3];
#pragma unroll
    for (int j = -1; j <= 1; j++) {
        int xc = min(max(x + j, 0), W - 1);
        // vertical pass then horizontal pass, matching reference op order
        v[j + 1] = (img[yu * W + xc] + 2.0f * img[y * W + xc] + img[yd * W + xc]) / 4.0f;
    }
    return (v[0] + 2.0f * v[1] + v[2]) / 4.0f;
}

__global__ void blur_kernel(const float* __restrict__ cur, const float* __restrict__ prev) {
    int x = blockIdx.x * blockDim.x + threadIdx.x;
    int y = blockIdx.y * blockDim.y + threadIdx.y;
    if (x >= W || y >= H) return;
    float bc = blur_at(cur, y, x);
    float bp = blur_at(prev, y, x);
    g_cur_blur[y * W + x] = bc;
    g_cur_q[y * W + x]  = (unsigned char)fminf(fmaxf(rintf(bc * 255.0f), 0.0f), 255.0f);
    g_prev_q[y * W + x] = (unsigned char)fminf(fmaxf(rintf(bp * 255.0f), 0.0f), 255.0f);
}

// ---------------- SAD block matching with spiral tie-break -----------------
__global__ void match_kernel() {
    __shared__ unsigned char win[WIN][WIN];
    __shared__ unsigned char tp[T][T];
    __shared__ int keys[128];

    const int bx = blockIdx.x, by = blockIdx.y;
    const int t  = threadIdx.x;

    // load 16x16 search window (edge-clamped prev_q)
    for (int i = t; i < WIN * WIN; i += 128) {
        int wy = i / WIN, wx = i % WIN;
        int gy = min(max(by * T - R + wy, 0), H - 1);
        int gx = min(max(bx * T - R + wx, 0), W - 1);
        win[wy][wx] = g_prev_q[gy * W + gx];
    }
    // load 8x8 template (cur_q)
    if (t < T * T) {
        int ty = t / T, tx = t % T;
        tp[ty][tx] = g_cur_q[(by * T + ty) * W + bx * T + tx];
    }
    __syncthreads();

    int key = 0x7fffffff;
    if (t < NC) {
        int cy = t / (2*R+1);   // dy + R  in [0,8]
        int cx = t % (2*R+1);   // dx + R
        int sad = 0;
#pragma unroll
        for (int ty = 0; ty < T; ty++)
#pragma unroll
            for (int tx = 0; tx < T; tx++)
                sad += abs((int)win[ty + cy][tx + cx] - (int)tp[ty][tx]);
        // cost (<=16320), then spiral rank (1..81), then unique cand id
        key = ((sad * 128 + g_spiral[t]) << 7) | t;
    }
    keys[t] = key;
    __syncthreads();
#pragma unroll
    for (int s = 64; s > 0; s >>= 1) {
        if (t < s) keys[t] = min(keys[t], keys[t + s]);
        __syncthreads();
    }
    if (t == 0) {
        int c  = keys[0] & 127;
        int dy = c / (2*R+1) - R;
        int dx = c % (2*R+1) - R;
        g_vec[by * WB + bx] = make_char2((char)(-dy), (char)(-dx));
    }
}

// ---------------- 3x3 vector median + LK subpixel + flow output ------------
__device__ __forceinline__ int median9(int* v) {
#pragma unroll
    for (int i = 1; i < 9; i++) {
        int k = v[i], j = i - 1;
        while (j >= 0 && v[j] > k) { v[j + 1] = v[j]; j--; }
        v[j + 1] = k;
    }
    return v[4];
}

__global__ void flow_kernel(float* __restrict__ out) {
    int gwarp = (blockIdx.x * blockDim.x + threadIdx.x) >> 5;
    int lane  = threadIdx.x & 31;
    if (gwarp >= HB * WB) return;
    int by = gwarp / WB, bx = gwarp % WB;

    int medy = 0, medx = 0;
    if (lane == 0) {
        int vy[9], vx[9];
#pragma unroll
        for (int k = 0; k < 9; k++) {
            int ny = min(max(by + k / 3 - 1, 0), HB - 1);
            int nx = min(max(bx + k % 3 - 1, 0), WB - 1);
            char2 v = g_vec[ny * WB + nx];
            vy[k] = v.x; vx[k] = v.y;
        }
        medy = median9(vy);
        medx = median9(vx);
    }
    medy = __shfl_sync(0xffffffffu, medy, 0);
    medx = __shfl_sync(0xffffffffu, medx, 0);
    int offy = -medy, offx = -medx;   // already in [-R,R], integral

    float a = 0.f, b = 0.f, d = 0.f, p = 0.f, q = 0.f;
#pragma unroll
    for (int rep = 0; rep < 2; rep++) {
        int i = lane + rep * 32;
        int ty = i / T, tx = i % T;
        bool pred = (ty == 0 || ty == T - 1 || tx == 0 || tx == T - 1);
        if (pred) {
            int gy0 = by * T + ty, gx0 = bx * T + tx;
            float gyv = (g_cur_blur[min(gy0 + 1, H - 1) * W + gx0] -
                         g_cur_blur[max(gy0 - 1, 0)     * W + gx0]) / 2.0f;
            float gxv = (g_cur_blur[gy0 * W + min(gx0 + 1, W - 1)] -
                         g_cur_blur[gy0 * W + max(gx0 - 1, 0)]) / 2.0f;
            float tmpl = (float)g_cur_q[gy0 * W + gx0] / 255.0f;
            int my = min(max(gy0 + offy, 0), H - 1);
            int mx = min(max(gx0 + offx, 0), W - 1);
            float mat  = (float)g_prev_q[my * W + mx] / 255.0f;
            float diff = mat - tmpl;
            a += gxv * gxv;
            b += gxv * gyv;
            d += gyv * gyv;
            p += diff * gxv;
            q += diff * gyv;
        }
    }
#pragma unroll
    for (int s = 16; s > 0; s >>= 1) {
        a += __shfl_down_sync(0xffffffffu, a, s);
        b += __shfl_down_sync(0xffffffffu, b, s);
        d += __shfl_down_sync(0xffffffffu, d, s);
        p += __shfl_down_sync(0xffffffffu, p, s);
        q += __shfl_down_sync(0xffffffffu, q, s);
    }
    if (lane == 0) {
        float det = a * d - b * b;
        bool  bad = (det <= 1e-6f);
        float sd  = bad ? 1.0f : det;
        float su  = (d * p - b * q) / sd;   // x-subpixel
        float sv  = (a * q - b * p) / sd;   // y-subpixel
        float subv = (bad || fabsf(sv) >= 1.0f) ? 0.0f : sv;
        float subu = (bad || fabsf(su) >= 1.0f) ? 0.0f : su;
        out[0 * HB * WB + by * WB + bx] = (float)medy + subv;
        out[1 * HB * WB + by * WB + bx] = (float)medx + subu;
    }
}

// ---------------- entry point ----------------------------------------------
extern "C" void kernel_launch(void* const* d_in, const int* in_sizes, int n_in,
                              void* d_out, int out_size) {
    const float* cur  = (const float*)d_in[0];
    const float* prev = (const float*)d_in[1];
    float* out = (float*)d_out;

    spiral_init_kernel<<<1, 1>>>();

    dim3 bt(32, 8);
    dim3 bg((W + 31) / 32, (H + 7) / 8);
    blur_kernel<<<bg, bt>>>(cur, prev);

    dim3 mg(WB, HB);
    match_kernel<<<mg, 128>>>();

    int nwarps  = HB * WB;
    int threads = 256;
    int blocks  = (nwarps * 32 + threads - 1) / threads;
    flow_kernel<<<blocks, threads>>>(out);
}

// round 2
// speedup vs baseline: 2.0732x; 2.0732x over previous
#include <cuda_runtime.h>

// Problem constants (fixed by setup_inputs: img [1,1,544,960], T=8, R=4)
#define H  544
#define W  960
#define T  8
#define R  4
#define HB (H/T)                  // 68
#define WB (W/T)                  // 120
#define NB (HB*WB)                // 8160
#define NC ((2*R+1)*(2*R+1))      // 81
#define WIN (T + 2*R)             // 16

// ---------------- scratch (device globals) ----------------------------------
__device__ float         g_cur_blur[H*W];
__device__ unsigned char g_cur_q[H*W];
__device__ unsigned char g_prev_q[H*W];
__device__ char2         g_vec[NB];     // (vy, vx) = (-dy, -dx)

// spiral rank LUT (row-major over (dy+R, dx+R)), precomputed for R=4
__constant__ unsigned char c_spiral[NC] = {
    74, 73, 72, 71, 70, 69, 68, 67, 66,
    75, 44, 43, 42, 41, 40, 39, 38, 65,
    76, 45, 22, 21, 20, 19, 18, 37, 64,
    77, 46, 23,  8,  7,  6, 17, 36, 63,
    78, 47, 24,  9,  1,  5, 16, 35, 62,
    79, 48, 25,  2,  3,  4, 15, 34, 61,
    80, 49, 10, 11, 12, 13, 14, 33, 60,
    81, 26, 27, 28, 29, 30, 31, 32, 59,
    50, 51, 52, 53, 54, 55, 56, 57, 58
};

// ---------------- binomial blur + uint8 quantization (4 px / thread) --------
__device__ __forceinline__ unsigned char quant8(float v) {
    return (unsigned char)fminf(fmaxf(rintf(v * 255.0f), 0.0f), 255.0f);
}

__global__ void blur_kernel(const float* __restrict__ cur, const float* __restrict__ prev) {
    int x4 = (blockIdx.x * blockDim.x + threadIdx.x) * 4;
    int y  =  blockIdx.y * blockDim.y + threadIdx.y;
    if (x4 >= W || y >= H) return;

    int yu = max(y - 1, 0) * W;
    int ym = y * W;
    int yd = min(y + 1, H - 1) * W;
    int idx[6];
    idx[0] = max(x4 - 1, 0);
    idx[1] = x4; idx[2] = x4 + 1; idx[3] = x4 + 2; idx[4] = x4 + 3;
    idx[5] = min(x4 + 4, W - 1);

    // cur image: store blur + quantized
    {
        float v[6];
#pragma unroll
        for (int j = 0; j < 6; j++)
            v[j] = (cur[yu + idx[j]] + 2.0f * cur[ym + idx[j]] + cur[yd + idx[j]]) * 0.25f;
        float4 o;
        o.x = (v[0] + 2.0f * v[1] + v[2]) * 0.25f;
        o.y = (v[1] + 2.0f * v[2] + v[3]) * 0.25f;
        o.z = (v[2] + 2.0f * v[3] + v[4]) * 0.25f;
        o.w = (v[3] + 2.0f * v[4] + v[5]) * 0.25f;
        *(float4*)&g_cur_blur[ym + x4] = o;
        uchar4 q = make_uchar4(quant8(o.x), quant8(o.y), quant8(o.z), quant8(o.w));
        *(uchar4*)&g_cur_q[ym + x4] = q;
    }
    // prev image: quantized only
    {
        float v[6];
#pragma unroll
        for (int j = 0; j < 6; j++)
            v[j] = (prev[yu + idx[j]] + 2.0f * prev[ym + idx[j]] + prev[yd + idx[j]]) * 0.25f;
        float4 o;
        o.x = (v[0] + 2.0f * v[1] + v[2]) * 0.25f;
        o.y = (v[1] + 2.0f * v[2] + v[3]) * 0.25f;
        o.z = (v[2] + 2.0f * v[3] + v[4]) * 0.25f;
        o.w = (v[3] + 2.0f * v[4] + v[5]) * 0.25f;
        uchar4 q = make_uchar4(quant8(o.x), quant8(o.y), quant8(o.z), quant8(o.w));
        *(uchar4*)&g_prev_q[ym + x4] = q;
    }
}

// ---------------- SAD matching: warp per block, __vsadu4 SIMD ---------------
__global__ void match_kernel() {
    // padded rows: 5 words so row[bw+2] never reads OOB (cx==8 -> bw=2, k8=0)
    __shared__ unsigned win[8][WIN][5];

    const int wid  = threadIdx.x >> 5;
    const int lane = threadIdx.x & 31;
    const int blk  = blockIdx.x * 8 + wid;
    if (blk >= NB) return;
    const int by = blk / WB, bx = blk % WB;

    // ---- load 16x16 search window of prev_q (2 rows of 8B per lane) ----
    {
        const int wy  = lane >> 1;
        const int wx0 = (lane & 1) * 8;
        const bool interior = (by >= 1 && by <= HB - 2 && bx >= 1 && bx <= WB - 2);
        unsigned lo, hi;
        if (interior) {
            const unsigned char* p = g_prev_q + (by * T - R + wy) * W + bx * T - R + wx0;
            lo = *(const unsigned*)p;         // 4B aligned (offset ≡ 4 mod 8)
            hi = *(const unsigned*)(p + 4);
        } else {
            lo = 0; hi = 0;
            int gy = min(max(by * T - R + wy, 0), H - 1);
#pragma unroll
            for (int b = 0; b < 4; b++) {
                int gx = min(max(bx * T - R + wx0 + b, 0), W - 1);
                lo |= (unsigned)g_prev_q[gy * W + gx] << (8 * b);
            }
#pragma unroll
            for (int b = 0; b < 4; b++) {
                int gx = min(max(bx * T - R + wx0 + 4 + b, 0), W - 1);
                hi |= (unsigned)g_prev_q[gy * W + gx] << (8 * b);
            }
        }
        win[wid][wy][wx0 >> 2]       = lo;
        win[wid][wy][(wx0 >> 2) + 1] = hi;
    }

    // ---- template rows in registers (broadcast loads, 8B aligned) ----
    unsigned tlo[T], thi[T];
#pragma unroll
    for (int ty = 0; ty < T; ty++) {
        uint2 t = *(const uint2*)(g_cur_q + (by * T + ty) * W + bx * T);
        tlo[ty] = t.x; thi[ty] = t.y;
    }
    __syncwarp();

    // ---- 81 candidates over 32 lanes (up to 3 each) ----
    unsigned key = 0xffffffffu;
#pragma unroll
    for (int j = 0; j < 3; j++) {
        int c = lane + j * 32;
        if (c < NC) {
            int cy = c / 9, cx = c - cy * 9;
            int k8 = (cx & 3) * 8, bw = cx >> 2;
            unsigned sad = 0;
#pragma unroll
            for (int ty = 0; ty < T; ty++) {
                const unsigned* row = &win[wid][ty + cy][0];
                unsigned w0 = row[bw], w1 = row[bw + 1], w2 = row[bw + 2];
                unsigned lo = __funnelshift_r(w0, w1, k8);
                unsigned hi = __funnelshift_r(w1, w2, k8);
                sad += __vsadu4(lo, tlo[ty]) + __vsadu4(hi, thi[ty]);
            }
            unsigned kk = ((sad * 128u + (unsigned)c_spiral[c]) << 7) | (unsigned)c;
            key = min(key, kk);
        }
    }
#pragma unroll
    for (int s = 16; s > 0; s >>= 1)
        key = min(key, __shfl_xor_sync(0xffffffffu, key, s));

    if (lane == 0) {
        int c  = key & 127;
        int dy = c / 9 - R;
        int dx = c % 9 - R;
        g_vec[blk] = make_char2((char)(-dy), (char)(-dx));
    }
}

// ---------------- branchless median of 9 (Paeth network) --------------------
#define SW(a,b) { int _t = min(a,b); b = max(a,b); a = _t; }
__device__ __forceinline__ int med9(int v0, int v1, int v2, int v3, int v4,
                                    int v5, int v6, int v7, int v8) {
    SW(v1,v2) SW(v4,v5) SW(v7,v8)
    SW(v0,v1) SW(v3,v4) SW(v6,v7)
    SW(v1,v2) SW(v4,v5) SW(v7,v8)
    SW(v0,v3) SW(v5,v8) SW(v4,v7)
    SW(v3,v6) SW(v1,v4) SW(v2,v5)
    SW(v4,v7) SW(v4,v2) SW(v6,v4)
    SW(v4,v2)
    return v4;
}

// ---------------- median + LK subpixel + flow output (warp / block) ---------
__global__ void flow_kernel(float* __restrict__ out) {
    const int wid  = threadIdx.x >> 5;
    const int lane = threadIdx.x & 31;
    const int blk  = blockIdx.x * 8 + wid;
    if (blk >= NB) return;
    const int by = blk / WB, bx = blk % WB;

    // lanes 0..8 load the 3x3 neighborhood of vectors
    int vy = 0, vx = 0;
    if (lane < 9) {
        int ny = min(max(by + lane / 3 - 1, 0), HB - 1);
        int nx = min(max(bx + lane % 3 - 1, 0), WB - 1);
        char2 v = g_vec[ny * WB + nx];
        vy = v.x; vx = v.y;
    }
    int ay[9], ax[9];
#pragma unroll
    for (int k = 0; k < 9; k++) {
        ay[k] = __shfl_sync(0xffffffffu, vy, k);
        ax[k] = __shfl_sync(0xffffffffu, vx, k);
    }
    int medy = med9(ay[0],ay[1],ay[2],ay[3],ay[4],ay[5],ay[6],ay[7],ay[8]);
    int medx = med9(ax[0],ax[1],ax[2],ax[3],ax[4],ax[5],ax[6],ax[7],ax[8]);
    int offy = -medy, offx = -medx;

    // lane -> border pixel (28 border pixels of the 8x8 block)
    int ty, tx;
    bool act = lane < 28;
    if      (lane < 8)  { ty = 0;         tx = lane;      }
    else if (lane < 16) { ty = 7;         tx = lane - 8;  }
    else if (lane < 22) { ty = lane - 15; tx = 0;         }  // rows 1..6
    else                { ty = lane - 21; tx = 7;         }  // rows 1..6 (28-31 dummy)

    float a = 0.f, b = 0.f, d = 0.f, p = 0.f, q = 0.f;
    if (act) {
        int gy0 = by * T + ty, gx0 = bx * T + tx;
        float gyv = (g_cur_blur[min(gy0 + 1, H - 1) * W + gx0] -
                     g_cur_blur[max(gy0 - 1, 0)     * W + gx0]) * 0.5f;
        float gxv = (g_cur_blur[gy0 * W + min(gx0 + 1, W - 1)] -
                     g_cur_blur[gy0 * W + max(gx0 - 1, 0)]) * 0.5f;
        float tmpl = (float)g_cur_q[gy0 * W + gx0] * (1.0f / 255.0f);
        int my = min(max(gy0 + offy, 0), H - 1);
        int mx = min(max(gx0 + offx, 0), W - 1);
        float mat  = (float)g_prev_q[my * W + mx] * (1.0f / 255.0f);
        float diff = mat - tmpl;
        a = gxv * gxv;
        b = gxv * gyv;
        d = gyv * gyv;
        p = diff * gxv;
        q = diff * gyv;
    }
#pragma unroll
    for (int s = 16; s > 0; s >>= 1) {
        a += __shfl_xor_sync(0xffffffffu, a, s);
        b += __shfl_xor_sync(0xffffffffu, b, s);
        d += __shfl_xor_sync(0xffffffffu, d, s);
        p += __shfl_xor_sync(0xffffffffu, p, s);
        q += __shfl_xor_sync(0xffffffffu, q, s);
    }
    if (lane == 0) {
        float det = a * d - b * b;
        bool  bad = (det <= 1e-6f);
        float sd  = bad ? 1.0f : det;
        float su  = (d * p - b * q) / sd;
        float sv  = (a * q - b * p) / sd;
        float subv = (bad || fabsf(sv) >= 1.0f) ? 0.0f : sv;
        float subu = (bad || fabsf(su) >= 1.0f) ? 0.0f : su;
        out[blk]      = (float)medy + subv;
        out[NB + blk] = (float)medx + subu;
    }
}

// ---------------- entry point ------------------------------------------------
extern "C" void kernel_launch(void* const* d_in, const int* in_sizes, int n_in,
                              void* d_out, int out_size) {
    const float* cur  = (const float*)d_in[0];
    const float* prev = (const float*)d_in[1];
    float* out = (float*)d_out;

    dim3 bt(64, 4);
    dim3 bg((W / 4 + 63) / 64, (H + 3) / 4);
    blur_kernel<<<bg, bt>>>(cur, prev);

    match_kernel<<<(NB + 7) / 8, 256>>>();
    flow_kernel<<<(NB + 7) / 8, 256>>>(out);
}

// round 3
// speedup vs baseline: 2.0763x; 1.0015x over previous
#include <cuda_runtime.h>

// Problem constants (fixed by setup_inputs: img [1,1,544,960], T=8, R=4)
#define H  544
#define W  960
#define T  8
#define R  4
#define HB (H/T)                  // 68
#define WB (W/T)                  // 120
#define NB (HB*WB)                // 8160
#define NC ((2*R+1)*(2*R+1))      // 81
#define WIN (T + 2*R)             // 16

// ---------------- scratch (device globals) ----------------------------------
__device__ float         g_cur_blur[H*W];
__device__ unsigned char g_cur_q[H*W];
__device__ unsigned char g_prev_q[H*W];
__device__ char2         g_vec[NB];     // (vy, vx) = (-dy, -dx)

// spiral rank LUT (row-major over (dy+R, dx+R)), precomputed for R=4
__constant__ unsigned char c_spiral[NC] = {
    74, 73, 72, 71, 70, 69, 68, 67, 66,
    75, 44, 43, 42, 41, 40, 39, 38, 65,
    76, 45, 22, 21, 20, 19, 18, 37, 64,
    77, 46, 23,  8,  7,  6, 17, 36, 63,
    78, 47, 24,  9,  1,  5, 16, 35, 62,
    79, 48, 25,  2,  3,  4, 15, 34, 61,
    80, 49, 10, 11, 12, 13, 14, 33, 60,
    81, 26, 27, 28, 29, 30, 31, 32, 59,
    50, 51, 52, 53, 54, 55, 56, 57, 58
};

// ---------------- binomial blur + uint8 quantization (2 px / thread) --------
__device__ __forceinline__ unsigned char quant8(float v) {
    return (unsigned char)fminf(fmaxf(rintf(v * 255.0f), 0.0f), 255.0f);
}

// blockDim (32,8): warp = 32 lanes covering 64 consecutive px in x.
__global__ void __launch_bounds__(256) blur_kernel(const float* __restrict__ cur,
                                                   const float* __restrict__ prev) {
    const int lane = threadIdx.x;
    const int x2   = (blockIdx.x * 32 + lane) * 2;            // W = 15*64 exactly
    const int y    = blockIdx.y * 8 + threadIdx.y;            // H = 68*8 exactly

    const int yu = max(y - 1, 0) * W;
    const int ym = y * W;
    const int yd = min(y + 1, H - 1) * W;
    const int xl = max(x2 - 1, 0);
    const int xr = min(x2 + 2, W - 1);

#pragma unroll
    for (int im = 0; im < 2; im++) {
        const float* __restrict__ img = im ? prev : cur;
        float2 u = *(const float2*)&img[yu + x2];
        float2 m = *(const float2*)&img[ym + x2];
        float2 d = *(const float2*)&img[yd + x2];
        float v0 = (u.x + 2.0f * m.x + d.x) * 0.25f;
        float v1 = (u.y + 2.0f * m.y + d.y) * 0.25f;
        float vL = __shfl_up_sync(0xffffffffu, v1, 1);
        float vR = __shfl_down_sync(0xffffffffu, v0, 1);
        if (lane == 0)
            vL = (img[yu + xl] + 2.0f * img[ym + xl] + img[yd + xl]) * 0.25f;
        if (lane == 31)
            vR = (img[yu + xr] + 2.0f * img[ym + xr] + img[yd + xr]) * 0.25f;
        float o0 = (vL + 2.0f * v0 + v1) * 0.25f;
        float o1 = (v0 + 2.0f * v1 + vR) * 0.25f;
        if (im == 0) {
            *(float2*)&g_cur_blur[ym + x2] = make_float2(o0, o1);
            *(uchar2*)&g_cur_q[ym + x2]    = make_uchar2(quant8(o0), quant8(o1));
        } else {
            *(uchar2*)&g_prev_q[ym + x2]   = make_uchar2(quant8(o0), quant8(o1));
        }
    }
}

// ---------------- SAD matching: warp per block, __vsadu4 SIMD ---------------
__global__ void __launch_bounds__(256) match_kernel() {
    // padded rows: 5 words so row[bw+2] never reads OOB (cx==8 -> bw=2, k8=0)
    __shared__ unsigned win[8][WIN][5];

    const int wid  = threadIdx.x >> 5;
    const int lane = threadIdx.x & 31;
    const int blk  = blockIdx.x * 8 + wid;       // NB = 1020*8 exactly
    const int by = blk / WB, bx = blk % WB;

    // ---- load 16x16 search window of prev_q (2 rows of 8B per lane) ----
    {
        const int wy  = lane >> 1;
        const int wx0 = (lane & 1) * 8;
        const bool interior = (by >= 1 && by <= HB - 2 && bx >= 1 && bx <= WB - 2);
        unsigned lo, hi;
        if (interior) {
            const unsigned char* p = g_prev_q + (by * T - R + wy) * W + bx * T - R + wx0;
            lo = *(const unsigned*)p;
            hi = *(const unsigned*)(p + 4);
        } else {
            lo = 0; hi = 0;
            int gy = min(max(by * T - R + wy, 0), H - 1);
#pragma unroll
            for (int b = 0; b < 4; b++) {
                int gx = min(max(bx * T - R + wx0 + b, 0), W - 1);
                lo |= (unsigned)g_prev_q[gy * W + gx] << (8 * b);
            }
#pragma unroll
            for (int b = 0; b < 4; b++) {
                int gx = min(max(bx * T - R + wx0 + 4 + b, 0), W - 1);
                hi |= (unsigned)g_prev_q[gy * W + gx] << (8 * b);
            }
        }
        win[wid][wy][wx0 >> 2]       = lo;
        win[wid][wy][(wx0 >> 2) + 1] = hi;
    }

    // ---- template rows in registers (broadcast loads, 8B aligned) ----
    unsigned tlo[T], thi[T];
#pragma unroll
    for (int ty = 0; ty < T; ty++) {
        uint2 t = *(const uint2*)(g_cur_q + (by * T + ty) * W + bx * T);
        tlo[ty] = t.x; thi[ty] = t.y;
    }
    __syncwarp();

    // ---- 81 candidates over 32 lanes (up to 3 each) ----
    unsigned key = 0xffffffffu;
#pragma unroll
    for (int j = 0; j < 3; j++) {
        int c = lane + j * 32;
        if (c < NC) {
            int cy = c / 9, cx = c - cy * 9;
            int k8 = (cx & 3) * 8, bw = cx >> 2;
            unsigned sad = 0;
#pragma unroll
            for (int ty = 0; ty < T; ty++) {
                const unsigned* row = &win[wid][ty + cy][0];
                unsigned w0 = row[bw], w1 = row[bw + 1], w2 = row[bw + 2];
                unsigned lo = __funnelshift_r(w0, w1, k8);
                unsigned hi = __funnelshift_r(w1, w2, k8);
                sad += __vsadu4(lo, tlo[ty]) + __vsadu4(hi, thi[ty]);
            }
            unsigned kk = ((sad * 128u + (unsigned)c_spiral[c]) << 7) | (unsigned)c;
            key = min(key, kk);
        }
    }
#pragma unroll
    for (int s = 16; s > 0; s >>= 1)
        key = min(key, __shfl_xor_sync(0xffffffffu, key, s));

    if (lane == 0) {
        int c  = key & 127;
        int dy = c / 9 - R;
        int dx = c % 9 - R;
        g_vec[blk] = make_char2((char)(-dy), (char)(-dx));
    }
}

// ---------------- packed byte-SIMD median of 9 (Paeth network) --------------
#define SWU(a,b) { unsigned _t = __vminu4(a,b); b = __vmaxu4(a,b); a = _t; }
__device__ __forceinline__ unsigned med9u(unsigned v0, unsigned v1, unsigned v2,
                                          unsigned v3, unsigned v4, unsigned v5,
                                          unsigned v6, unsigned v7, unsigned v8) {
    SWU(v1,v2) SWU(v4,v5) SWU(v7,v8)
    SWU(v0,v1) SWU(v3,v4) SWU(v6,v7)
    SWU(v1,v2) SWU(v4,v5) SWU(v7,v8)
    SWU(v0,v3) SWU(v5,v8) SWU(v4,v7)
    SWU(v3,v6) SWU(v1,v4) SWU(v2,v5)
    SWU(v4,v7) SWU(v4,v2) SWU(v6,v4)
    SWU(v4,v2)
    return v4;
}

// ---------------- median + LK subpixel + flow output (warp / block) ---------
__global__ void __launch_bounds__(256) flow_kernel(float* __restrict__ out) {
    const int wid  = threadIdx.x >> 5;
    const int lane = threadIdx.x & 31;
    const int blk  = blockIdx.x * 8 + wid;       // NB = 1020*8 exactly
    const int by = blk / WB, bx = blk % WB;

    // lanes 0..8 load the 3x3 neighborhood; pack (vy+4) | (vx+4)<<8
    unsigned pk = 0;
    if (lane < 9) {
        int ny = min(max(by + lane / 3 - 1, 0), HB - 1);
        int nx = min(max(bx + lane % 3 - 1, 0), WB - 1);
        char2 v = g_vec[ny * WB + nx];
        pk = (unsigned)(v.x + 4) | ((unsigned)(v.y + 4) << 8);
    }
    unsigned a0 = __shfl_sync(0xffffffffu, pk, 0);
    unsigned a1 = __shfl_sync(0xffffffffu, pk, 1);
    unsigned a2 = __shfl_sync(0xffffffffu, pk, 2);
    unsigned a3 = __shfl_sync(0xffffffffu, pk, 3);
    unsigned a4 = __shfl_sync(0xffffffffu, pk, 4);
    unsigned a5 = __shfl_sync(0xffffffffu, pk, 5);
    unsigned a6 = __shfl_sync(0xffffffffu, pk, 6);
    unsigned a7 = __shfl_sync(0xffffffffu, pk, 7);
    unsigned a8 = __shfl_sync(0xffffffffu, pk, 8);
    unsigned md = med9u(a0,a1,a2,a3,a4,a5,a6,a7,a8);
    int medy = (int)(md & 0xff) - 4;
    int medx = (int)((md >> 8) & 0xff) - 4;
    int offy = -medy, offx = -medx;

    // lane -> border pixel (28 border pixels of the 8x8 block)
    int ty, tx;
    bool act = lane < 28;
    if      (lane < 8)  { ty = 0;         tx = lane;      }
    else if (lane < 16) { ty = 7;         tx = lane - 8;  }
    else if (lane < 22) { ty = lane - 15; tx = 0;         }
    else                { ty = lane - 21; tx = 7;         }

    float a = 0.f, b = 0.f, d = 0.f, p = 0.f, q = 0.f;
    if (act) {
        int gy0 = by * T + ty, gx0 = bx * T + tx;
        float gyv = (g_cur_blur[min(gy0 + 1, H - 1) * W + gx0] -
                     g_cur_blur[max(gy0 - 1, 0)     * W + gx0]) * 0.5f;
        float gxv = (g_cur_blur[gy0 * W + min(gx0 + 1, W - 1)] -
                     g_cur_blur[gy0 * W + max(gx0 - 1, 0)]) * 0.5f;
        float tmpl = (float)g_cur_q[gy0 * W + gx0] * (1.0f / 255.0f);
        int my = min(max(gy0 + offy, 0), H - 1);
        int mx = min(max(gx0 + offx, 0), W - 1);
        float mat  = (float)g_prev_q[my * W + mx] * (1.0f / 255.0f);
        float diff = mat - tmpl;
        a = gxv * gxv;
        b = gxv * gyv;
        d = gyv * gyv;
        p = diff * gxv;
        q = diff * gyv;
    }
#pragma unroll
    for (int s = 16; s > 0; s >>= 1) {
        a += __shfl_xor_sync(0xffffffffu, a, s);
        b += __shfl_xor_sync(0xffffffffu, b, s);
        d += __shfl_xor_sync(0xffffffffu, d, s);
        p += __shfl_xor_sync(0xffffffffu, p, s);
        q += __shfl_xor_sync(0xffffffffu, q, s);
    }
    if (lane == 0) {
        float det = a * d - b * b;
        bool  bad = (det <= 1e-6f);
        float sd  = bad ? 1.0f : det;
        float su  = (d * p - b * q) / sd;
        float sv  = (a * q - b * p) / sd;
        float subv = (bad || fabsf(sv) >= 1.0f) ? 0.0f : sv;
        float subu = (bad || fabsf(su) >= 1.0f) ? 0.0f : su;
        out[blk]      = (float)medy + subv;
        out[NB + blk] = (float)medx + subu;
    }
}

// ---------------- entry point ------------------------------------------------
extern "C" void kernel_launch(void* const* d_in, const int* in_sizes, int n_in,
                              void* d_out, int out_size) {
    const float* cur  = (const float*)d_in[0];
    const float* prev = (const float*)d_in[1];
    float* out = (float*)d_out;

    dim3 bt(32, 8);
    dim3 bg(W / 64, H / 8);              // 15 x 68 = 1020 blocks
    blur_kernel<<<bg, bt>>>(cur, prev);

    match_kernel<<<NB / 8, 256>>>();
    flow_kernel<<<NB / 8, 256>>>(out);
}

// round 4
// speedup vs baseline: 2.2934x; 1.1046x over previous
#include <cuda_runtime.h>

// Problem constants (fixed by setup_inputs: img [1,1,544,960], T=8, R=4)
#define H  544
#define W  960
#define T  8
#define R  4
#define HB (H/T)                  // 68
#define WB (W/T)                  // 120
#define NB (HB*WB)                // 8160
#define NC ((2*R+1)*(2*R+1))      // 81
#define WIN (T + 2*R)             // 16

// ---------------- scratch (device globals) ----------------------------------
__device__ float         g_cur_blur[H*W];
__device__ unsigned char g_cur_q[H*W];
__device__ unsigned char g_prev_q[H*W];
__device__ char2         g_vec[NB];     // (vy, vx) = (-dy, -dx)

// spiral rank LUT (row-major over (dy+R, dx+R)), precomputed for R=4
__constant__ unsigned char c_spiral[NC] = {
    74, 73, 72, 71, 70, 69, 68, 67, 66,
    75, 44, 43, 42, 41, 40, 39, 38, 65,
    76, 45, 22, 21, 20, 19, 18, 37, 64,
    77, 46, 23,  8,  7,  6, 17, 36, 63,
    78, 47, 24,  9,  1,  5, 16, 35, 62,
    79, 48, 25,  2,  3,  4, 15, 34, 61,
    80, 49, 10, 11, 12, 13, 14, 33, 60,
    81, 26, 27, 28, 29, 30, 31, 32, 59,
    50, 51, 52, 53, 54, 55, 56, 57, 58
};

// ---------------- binomial blur + uint8 quantization -------------------------
// 2 rows x 2 cols per thread; vertical-pass reuse across the row pair.
__device__ __forceinline__ unsigned char quant8(float v) {
    return (unsigned char)fminf(fmaxf(rintf(v * 255.0f), 0.0f), 255.0f);
}

__global__ void __launch_bounds__(256) blur_kernel(const float* __restrict__ cur,
                                                   const float* __restrict__ prev) {
    const int lane = threadIdx.x;
    const int x2 = (blockIdx.x * 32 + lane) * 2;              // W = 15*64
    const int y0 = (blockIdx.y * 8 + threadIdx.y) * 2;        // H = 34*16
    const int r0 = max(y0 - 1, 0) * W;
    const int r1 = y0 * W;
    const int r2 = (y0 + 1) * W;
    const int r3 = min(y0 + 2, H - 1) * W;
    const int xl = max(x2 - 1, 0);
    const int xr = min(x2 + 2, W - 1);

#pragma unroll
    for (int im = 0; im < 2; im++) {
        const float* __restrict__ img = im ? prev : cur;
        float2 a0 = *(const float2*)&img[r0 + x2];
        float2 a1 = *(const float2*)&img[r1 + x2];
        float2 a2 = *(const float2*)&img[r2 + x2];
        float2 a3 = *(const float2*)&img[r3 + x2];
        float2 va, vb;
        va.x = (a0.x + 2.0f * a1.x + a2.x) * 0.25f;
        va.y = (a0.y + 2.0f * a1.y + a2.y) * 0.25f;
        vb.x = (a1.x + 2.0f * a2.x + a3.x) * 0.25f;
        vb.y = (a1.y + 2.0f * a2.y + a3.y) * 0.25f;
        float vaL = __shfl_up_sync(0xffffffffu, va.y, 1);
        float vaR = __shfl_down_sync(0xffffffffu, va.x, 1);
        float vbL = __shfl_up_sync(0xffffffffu, vb.y, 1);
        float vbR = __shfl_down_sync(0xffffffffu, vb.x, 1);
        if (lane == 0) {
            float e0 = img[r0 + xl], e1 = img[r1 + xl], e2 = img[r2 + xl], e3 = img[r3 + xl];
            vaL = (e0 + 2.0f * e1 + e2) * 0.25f;
            vbL = (e1 + 2.0f * e2 + e3) * 0.25f;
        }
        if (lane == 31) {
            float e0 = img[r0 + xr], e1 = img[r1 + xr], e2 = img[r2 + xr], e3 = img[r3 + xr];
            vaR = (e0 + 2.0f * e1 + e2) * 0.25f;
            vbR = (e1 + 2.0f * e2 + e3) * 0.25f;
        }
        float oa0 = (vaL + 2.0f * va.x + va.y) * 0.25f;
        float oa1 = (va.x + 2.0f * va.y + vaR) * 0.25f;
        float ob0 = (vbL + 2.0f * vb.x + vb.y) * 0.25f;
        float ob1 = (vb.x + 2.0f * vb.y + vbR) * 0.25f;
        if (im == 0) {
            *(float2*)&g_cur_blur[r1 + x2] = make_float2(oa0, oa1);
            *(float2*)&g_cur_blur[r2 + x2] = make_float2(ob0, ob1);
            *(uchar2*)&g_cur_q[r1 + x2]    = make_uchar2(quant8(oa0), quant8(oa1));
            *(uchar2*)&g_cur_q[r2 + x2]    = make_uchar2(quant8(ob0), quant8(ob1));
        } else {
            *(uchar2*)&g_prev_q[r1 + x2]   = make_uchar2(quant8(oa0), quant8(oa1));
            *(uchar2*)&g_prev_q[r2 + x2]   = make_uchar2(quant8(ob0), quant8(ob1));
        }
    }
    cudaTriggerProgrammaticLaunchCompletion();
}

// ---------------- SAD matching: warp per block, __vsadu4 SIMD ---------------
__global__ void __launch_bounds__(256) match_kernel() {
    __shared__ unsigned win[8][WIN][5];

    const int wid  = threadIdx.x >> 5;
    const int lane = threadIdx.x & 31;
    const int blk  = blockIdx.x * 8 + wid;       // NB = 1020*8 exactly
    const int by = blk / WB, bx = blk % WB;

    cudaGridDependencySynchronize();             // wait for blur results

    // ---- load 16x16 search window of prev_q (2 rows of 8B per lane) ----
    {
        const int wy  = lane >> 1;
        const int wx0 = (lane & 1) * 8;
        const bool interior = (by >= 1 && by <= HB - 2 && bx >= 1 && bx <= WB - 2);
        unsigned lo, hi;
        if (interior) {
            const unsigned char* p = g_prev_q + (by * T - R + wy) * W + bx * T - R + wx0;
            lo = *(const unsigned*)p;
            hi = *(const unsigned*)(p + 4);
        } else {
            lo = 0; hi = 0;
            int gy = min(max(by * T - R + wy, 0), H - 1);
#pragma unroll
            for (int b = 0; b < 4; b++) {
                int gx = min(max(bx * T - R + wx0 + b, 0), W - 1);
                lo |= (unsigned)g_prev_q[gy * W + gx] << (8 * b);
            }
#pragma unroll
            for (int b = 0; b < 4; b++) {
                int gx = min(max(bx * T - R + wx0 + 4 + b, 0), W - 1);
                hi |= (unsigned)g_prev_q[gy * W + gx] << (8 * b);
            }
        }
        win[wid][wy][wx0 >> 2]       = lo;
        win[wid][wy][(wx0 >> 2) + 1] = hi;
    }

    // ---- template rows in registers (broadcast loads, 8B aligned) ----
    unsigned tlo[T], thi[T];
#pragma unroll
    for (int ty = 0; ty < T; ty++) {
        uint2 t = *(const uint2*)(g_cur_q + (by * T + ty) * W + bx * T);
        tlo[ty] = t.x; thi[ty] = t.y;
    }
    __syncwarp();

    // ---- 81 candidates over 32 lanes (up to 3 each) ----
    unsigned key = 0xffffffffu;
#pragma unroll
    for (int j = 0; j < 3; j++) {
        int c = lane + j * 32;
        if (c < NC) {
            int cy = c / 9, cx = c - cy * 9;
            int k8 = (cx & 3) * 8, bw = cx >> 2;
            unsigned sad = 0;
#pragma unroll
            for (int ty = 0; ty < T; ty++) {
                const unsigned* row = &win[wid][ty + cy][0];
                unsigned w0 = row[bw], w1 = row[bw + 1], w2 = row[bw + 2];
                unsigned lo = __funnelshift_r(w0, w1, k8);
                unsigned hi = __funnelshift_r(w1, w2, k8);
                sad += __vsadu4(lo, tlo[ty]) + __vsadu4(hi, thi[ty]);
            }
            unsigned kk = ((sad * 128u + (unsigned)c_spiral[c]) << 7) | (unsigned)c;
            key = min(key, kk);
        }
    }
#pragma unroll
    for (int s = 16; s > 0; s >>= 1)
        key = min(key, __shfl_xor_sync(0xffffffffu, key, s));

    if (lane == 0) {
        int c  = key & 127;
        int dy = c / 9 - R;
        int dx = c % 9 - R;
        g_vec[blk] = make_char2((char)(-dy), (char)(-dx));
    }
    cudaTriggerProgrammaticLaunchCompletion();
}

// ---------------- packed byte-SIMD median of 9 (Paeth network) --------------
#define SWU(a,b) { unsigned _t = __vminu4(a,b); b = __vmaxu4(a,b); a = _t; }
__device__ __forceinline__ unsigned med9u(unsigned v0, unsigned v1, unsigned v2,
                                          unsigned v3, unsigned v4, unsigned v5,
                                          unsigned v6, unsigned v7, unsigned v8) {
    SWU(v1,v2) SWU(v4,v5) SWU(v7,v8)
    SWU(v0,v1) SWU(v3,v4) SWU(v6,v7)
    SWU(v1,v2) SWU(v4,v5) SWU(v7,v8)
    SWU(v0,v3) SWU(v5,v8) SWU(v4,v7)
    SWU(v3,v6) SWU(v1,v4) SWU(v2,v5)
    SWU(v4,v7) SWU(v4,v2) SWU(v6,v4)
    SWU(v4,v2)
    return v4;
}

// ---------------- median + LK subpixel + flow output (warp / block) ---------
__global__ void __launch_bounds__(256) flow_kernel(float* __restrict__ out) {
    const int wid  = threadIdx.x >> 5;
    const int lane = threadIdx.x & 31;
    const int blk  = blockIdx.x * 8 + wid;       // NB = 1020*8 exactly
    const int by = blk / WB, bx = blk % WB;

    // lane -> border pixel (28 border pixels of the 8x8 block)
    int ty, tx;
    bool act = lane < 28;
    if      (lane < 8)  { ty = 0;         tx = lane;      }
    else if (lane < 16) { ty = 7;         tx = lane - 8;  }
    else if (lane < 22) { ty = lane - 15; tx = 0;         }
    else                { ty = lane - 21; tx = 7;         }
    const int gy0 = by * T + ty, gx0 = bx * T + tx;

    cudaGridDependencySynchronize();             // wait for match results

    // lanes 0..8 load the 3x3 neighborhood; pack (vy+4) | (vx+4)<<8
    unsigned pk = 0;
    if (lane < 9) {
        int ny = min(max(by + lane / 3 - 1, 0), HB - 1);
        int nx = min(max(bx + lane % 3 - 1, 0), WB - 1);
        char2 v = g_vec[ny * WB + nx];
        pk = (unsigned)(v.x + 4) | ((unsigned)(v.y + 4) << 8);
    }
    unsigned a0 = __shfl_sync(0xffffffffu, pk, 0);
    unsigned a1 = __shfl_sync(0xffffffffu, pk, 1);
    unsigned a2 = __shfl_sync(0xffffffffu, pk, 2);
    unsigned a3 = __shfl_sync(0xffffffffu, pk, 3);
    unsigned a4 = __shfl_sync(0xffffffffu, pk, 4);
    unsigned a5 = __shfl_sync(0xffffffffu, pk, 5);
    unsigned a6 = __shfl_sync(0xffffffffu, pk, 6);
    unsigned a7 = __shfl_sync(0xffffffffu, pk, 7);
    unsigned a8 = __shfl_sync(0xffffffffu, pk, 8);
    unsigned md = med9u(a0,a1,a2,a3,a4,a5,a6,a7,a8);
    int medy = (int)(md & 0xff) - 4;
    int medx = (int)((md >> 8) & 0xff) - 4;
    int offy = -medy, offx = -medx;

    float a = 0.f, b = 0.f, d = 0.f, p = 0.f, q = 0.f;
    if (act) {
        float gyv = (g_cur_blur[min(gy0 + 1, H - 1) * W + gx0] -
                     g_cur_blur[max(gy0 - 1, 0)     * W + gx0]) * 0.5f;
        float gxv = (g_cur_blur[gy0 * W + min(gx0 + 1, W - 1)] -
                     g_cur_blur[gy0 * W + max(gx0 - 1, 0)]) * 0.5f;
        float tmpl = (float)g_cur_q[gy0 * W + gx0] * (1.0f / 255.0f);
        int my = min(max(gy0 + offy, 0), H - 1);
        int mx = min(max(gx0 + offx, 0), W - 1);
        float mat  = (float)g_prev_q[my * W + mx] * (1.0f / 255.0f);
        float diff = mat - tmpl;
        a = gxv * gxv;
        b = gxv * gyv;
        d = gyv * gyv;
        p = diff * gxv;
        q = diff * gyv;
    }
#pragma unroll
    for (int s = 16; s > 0; s >>= 1) {
        a += __shfl_xor_sync(0xffffffffu, a, s);
        b += __shfl_xor_sync(0xffffffffu, b, s);
        d += __shfl_xor_sync(0xffffffffu, d, s);
        p += __shfl_xor_sync(0xffffffffu, p, s);
        q += __shfl_xor_sync(0xffffffffu, q, s);
    }
    if (lane == 0) {
        float det = a * d - b * b;
        bool  bad = (det <= 1e-6f);
        float sd  = bad ? 1.0f : det;
        float su  = (d * p - b * q) / sd;
        float sv  = (a * q - b * p) / sd;
        float subv = (bad || fabsf(sv) >= 1.0f) ? 0.0f : sv;
        float subu = (bad || fabsf(su) >= 1.0f) ? 0.0f : su;
        out[blk]      = (float)medy + subv;
        out[NB + blk] = (float)medx + subu;
    }
}

// ---------------- entry point ------------------------------------------------
extern "C" void kernel_launch(void* const* d_in, const int* in_sizes, int n_in,
                              void* d_out, int out_size) {
    const float* cur  = (const float*)d_in[0];
    const float* prev = (const float*)d_in[1];
    float* out = (float*)d_out;

    // blur: plain launch
    {
        dim3 bt(32, 8);
        dim3 bg(W / 64, H / 16);         // 15 x 34
        blur_kernel<<<bg, bt>>>(cur, prev);
    }

    // match + flow: programmatic dependent launches (overlap launch latency)
    cudaLaunchAttribute attr[1];
    attr[0].id = cudaLaunchAttributeProgrammaticStreamSerialization;
    attr[0].val.programmaticStreamSerializationAllowed = 1;

    {
        cudaLaunchConfig_t cfg = {};
        cfg.gridDim  = dim3(NB / 8, 1, 1);
        cfg.blockDim = dim3(256, 1, 1);
        cfg.dynamicSmemBytes = 0;
        cfg.stream = 0;
        cfg.attrs = attr;
        cfg.numAttrs = 1;
        cudaLaunchKernelEx(&cfg, match_kernel);
    }
    {
        cudaLaunchConfig_t cfg = {};
        cfg.gridDim  = dim3(NB / 8, 1, 1);
        cfg.blockDim = dim3(256, 1, 1);
        cfg.dynamicSmemBytes = 0;
        cfg.stream = 0;
        cfg.attrs = attr;
        cfg.numAttrs = 1;
        cudaLaunchKernelEx(&cfg, flow_kernel, out);
    }
}